// round 1
// baseline (speedup 1.0000x reference)
#include <cuda_runtime.h>
#include <math.h>

// Problem dims
#define Bsz   8
#define Ssz   2048
#define DMdim 512
#define Hh    8
#define SDdim 64
#define INNER 512
#define HID   2048
#define MROWS (Bsz*Ssz)   // 16384

// ---------------- scratch (device globals: allocation-free) ----------------
__device__ float g_n [MROWS*DMdim];
__device__ float g_a [MROWS*INNER];
__device__ float g_b [MROWS*INNER];
__device__ float g_ql[MROWS*INNER];
__device__ float g_qr[MROWS*INNER];
__device__ float g_sd[MROWS*Hh];
__device__ float g_pd[MROWS*Hh];
__device__ float g_g [MROWS*INNER];
__device__ float g_r [MROWS*DMdim];
__device__ float g_l2[MROWS*DMdim];
__device__ float g_h [MROWS*HID];

// ---------------- LayerNorm: one block per row of 512 ----------------
__global__ __launch_bounds__(128)
void ln_kernel(const float* __restrict__ x, const float* __restrict__ gm,
               const float* __restrict__ bt, float* __restrict__ out)
{
    int row = blockIdx.x;
    int tid = threadIdx.x;                 // 128 threads, 1 float4 each (512 elems)
    const float4* xr = (const float4*)(x + (size_t)row * DMdim);
    float4 v = xr[tid];
    float s  = v.x + v.y + v.z + v.w;
    float s2 = v.x*v.x + v.y*v.y + v.z*v.z + v.w*v.w;
    #pragma unroll
    for (int o = 16; o > 0; o >>= 1) {
        s  += __shfl_xor_sync(0xffffffffu, s,  o);
        s2 += __shfl_xor_sync(0xffffffffu, s2, o);
    }
    __shared__ float ss[4], ss2[4];
    int wid = tid >> 5, lane = tid & 31;
    if (lane == 0) { ss[wid] = s; ss2[wid] = s2; }
    __syncthreads();
    s  = ss[0] + ss[1] + ss[2] + ss[3];
    s2 = ss2[0] + ss2[1] + ss2[2] + ss2[3];
    float m   = s * (1.0f / DMdim);
    float var = s2 * (1.0f / DMdim) - m * m;
    float inv = rsqrtf(var + 1e-5f);
    float4 gv = ((const float4*)gm)[tid];
    float4 bv = ((const float4*)bt)[tid];
    float4 o;
    o.x = (v.x - m) * inv * gv.x + bv.x;
    o.y = (v.y - m) * inv * gv.y + bv.y;
    o.z = (v.z - m) * inv * gv.z + bv.z;
    o.w = (v.w - m) * inv * gv.w + bv.w;
    ((float4*)(out + (size_t)row * DMdim))[tid] = o;
}

// ---------------- sd/pd gates: 16 sigmoid dots per row ----------------
__global__ __launch_bounds__(512)
void sdpd_kernel(const float* __restrict__ n,
                 const float* __restrict__ Wsd, const float* __restrict__ bsd,
                 const float* __restrict__ Wpd, const float* __restrict__ bpd,
                 float* __restrict__ sd, float* __restrict__ pd)
{
    int row = blockIdx.x;
    __shared__ float nr[DMdim];
    int tid = threadIdx.x;                 // 512
    nr[tid] = n[(size_t)row * DMdim + tid];
    __syncthreads();
    int w = tid >> 5, lane = tid & 31;     // 16 warps -> 16 outputs
    const float* Wt = (w < 8) ? (Wsd + (size_t)w * DMdim) : (Wpd + (size_t)(w - 8) * DMdim);
    float acc = 0.f;
    #pragma unroll
    for (int j = lane; j < DMdim; j += 32) acc += nr[j] * Wt[j];
    #pragma unroll
    for (int o = 16; o > 0; o >>= 1) acc += __shfl_xor_sync(0xffffffffu, acc, o);
    if (lane == 0) {
        int h = w & 7;
        float bias = (w < 8) ? bsd[h] : bpd[h];
        float v = 1.f / (1.f + expf(-(acc + bias)));
        if (w < 8) sd[(size_t)row * Hh + h] = v;
        else       pd[(size_t)row * Hh + h] = v;
    }
}

// ---------------- SGEMM: C[M,N] = A[M,K] @ B[N,K]^T (+epilogue) ----------------
// BM=BN=128, BK=16, 256 threads, 8x8 per thread. All dims divisible (no tails).
enum { EPI_TANH = 0, EPI_RES = 1, EPI_BIAS_GELU = 2, EPI_BIAS_RES = 3 };

template<int EPI>
__global__ __launch_bounds__(256)
void sgemm_kernel(const float* __restrict__ A, const float* __restrict__ Bw,
                  const float* __restrict__ bias, const float* __restrict__ resid,
                  float* __restrict__ C, int N, int K)
{
    const int BK = 16;
    __shared__ float As[BK][128];
    __shared__ float Bs[BK][128];
    int tid = threadIdx.x;
    int tx = tid & 15, ty = tid >> 4;
    int bn0 = blockIdx.x * 128, bm0 = blockIdx.y * 128;

    float acc[8][8];
    #pragma unroll
    for (int i = 0; i < 8; i++)
        #pragma unroll
        for (int j = 0; j < 8; j++) acc[i][j] = 0.f;

    for (int k0 = 0; k0 < K; k0 += BK) {
        #pragma unroll
        for (int c = 0; c < 2; c++) {
            int idx = tid + c * 256;
            int m  = idx >> 2;            // 0..127
            int kk = (idx & 3) << 2;      // 0,4,8,12
            float4 va = *(const float4*)(A  + (size_t)(bm0 + m) * K + k0 + kk);
            As[kk + 0][m] = va.x; As[kk + 1][m] = va.y;
            As[kk + 2][m] = va.z; As[kk + 3][m] = va.w;
            float4 vb = *(const float4*)(Bw + (size_t)(bn0 + m) * K + k0 + kk);
            Bs[kk + 0][m] = vb.x; Bs[kk + 1][m] = vb.y;
            Bs[kk + 2][m] = vb.z; Bs[kk + 3][m] = vb.w;
        }
        __syncthreads();
        #pragma unroll
        for (int kk = 0; kk < BK; kk++) {
            float4 a0 = *(const float4*)&As[kk][ty * 8];
            float4 a1 = *(const float4*)&As[kk][ty * 8 + 4];
            float4 b0 = *(const float4*)&Bs[kk][tx * 8];
            float4 b1 = *(const float4*)&Bs[kk][tx * 8 + 4];
            float ra[8] = {a0.x,a0.y,a0.z,a0.w,a1.x,a1.y,a1.z,a1.w};
            float rb[8] = {b0.x,b0.y,b0.z,b0.w,b1.x,b1.y,b1.z,b1.w};
            #pragma unroll
            for (int i = 0; i < 8; i++)
                #pragma unroll
                for (int j = 0; j < 8; j++)
                    acc[i][j] += ra[i] * rb[j];
        }
        __syncthreads();
    }

    #pragma unroll
    for (int i = 0; i < 8; i++) {
        int row = bm0 + ty * 8 + i;
        #pragma unroll
        for (int jv = 0; jv < 2; jv++) {
            int col = bn0 + tx * 8 + jv * 4;
            float v[4] = {acc[i][jv*4+0], acc[i][jv*4+1], acc[i][jv*4+2], acc[i][jv*4+3]};
            if (EPI == EPI_BIAS_GELU || EPI == EPI_BIAS_RES) {
                #pragma unroll
                for (int j = 0; j < 4; j++) v[j] += bias[col + j];
            }
            if (EPI == EPI_TANH) {
                #pragma unroll
                for (int j = 0; j < 4; j++) v[j] = tanhf(v[j]);
            }
            if (EPI == EPI_BIAS_GELU) {
                #pragma unroll
                for (int j = 0; j < 4; j++)
                    v[j] = 0.5f * v[j] * (1.f + erff(v[j] * 0.70710678118654752f));
            }
            if (EPI == EPI_RES || EPI == EPI_BIAS_RES) {
                float4 rv = *(const float4*)(resid + (size_t)row * N + col);
                v[0] += rv.x; v[1] += rv.y; v[2] += rv.z; v[3] += rv.w;
            }
            float4 o = {v[0], v[1], v[2], v[3]};
            *(float4*)(C + (size_t)row * N + col) = o;
        }
    }
}

// ---------------- pair-state scan ----------------
// grid = 128 blocks: (b,h) x 2 e-halves. 256 threads: e_local = tid>>3 (32),
// dq = tid&7. Each thread owns pair[d=dq*8+i][e] (8 regs). State in shared.
__global__ __launch_bounds__(256)
void pair_scan_kernel(const float* __restrict__ a,  const float* __restrict__ bm,
                      const float* __restrict__ ql, const float* __restrict__ qr,
                      const float* __restrict__ sd, const float* __restrict__ pd,
                      float* __restrict__ g)
{
    int blk = blockIdx.x;         // 0..127
    int eh  = blk & 1;
    int bh  = blk >> 1;           // 0..63
    int tid = threadIdx.x;
    int el  = tid >> 3;           // 0..31
    int dq  = tid & 7;            // 0..7
    int e   = eh * 32 + el;

    float p[8];
    #pragma unroll
    for (int i = 0; i < 8; i++) p[i] = 0.f;

    __shared__ float st[64], ash[64], bsh[64], qsh[64], rsh[32];
    __shared__ float spd[2];
    if (tid < 64) st[tid] = 0.f;

    size_t base  = (size_t)(bh >> 3) * Ssz * INNER + (size_t)(bh & 7) * SDdim;
    size_t base8 = (size_t)(bh >> 3) * Ssz * Hh + (bh & 7);
    __syncthreads();

    for (int t = 0; t < Ssz; t++) {
        if      (tid < 64)  ash[tid]       = a [base + tid];
        else if (tid < 128) bsh[tid - 64]  = bm[base + tid - 64];
        else if (tid < 192) qsh[tid - 128] = ql[base + tid - 128];
        else if (tid < 224) rsh[tid - 192] = qr[base + eh * 32 + (tid - 192)];
        else if (tid == 224) spd[0] = sd[base8];
        else if (tid == 225) spd[1] = pd[base8];
        __syncthreads();

        float pdv = spd[1];
        float c   = (1.f - pdv) * bsh[e];
        float4 s0 = *(const float4*)&st[dq * 8];
        float4 s1 = *(const float4*)&st[dq * 8 + 4];
        float4 q0 = *(const float4*)&qsh[dq * 8];
        float4 q1 = *(const float4*)&qsh[dq * 8 + 4];
        float sv[8] = {s0.x,s0.y,s0.z,s0.w,s1.x,s1.y,s1.z,s1.w};
        float qv[8] = {q0.x,q0.y,q0.z,q0.w,q1.x,q1.y,q1.z,q1.w};

        float lacc = 0.f;
        #pragma unroll
        for (int i = 0; i < 8; i++) {
            p[i] = pdv * p[i] + c * sv[i];   // pair update uses prev state
            lacc += p[i] * qv[i];            // lc uses the UPDATED pair
        }
        lacc += __shfl_xor_sync(0xffffffffu, lacc, 1);
        lacc += __shfl_xor_sync(0xffffffffu, lacc, 2);
        lacc += __shfl_xor_sync(0xffffffffu, lacc, 4);
        if (dq == 0) g[base + e] = lacc * rsh[el];
        __syncthreads();

        if (tid < 64) {                      // state update AFTER pair used prev
            float sdv = spd[0];
            st[tid] = sdv * st[tid] + (1.f - sdv) * ash[tid];
        }
        base  += INNER;
        base8 += Hh;
    }
}

// ---------------- launch ----------------
extern "C" void kernel_launch(void* const* d_in, const int* in_sizes, int n_in,
                              void* d_out, int out_size)
{
    const float* x    = (const float*)d_in[0];
    const float* ng   = (const float*)d_in[1];
    const float* nb   = (const float*)d_in[2];
    const float* fng  = (const float*)d_in[3];
    const float* fnb  = (const float*)d_in[4];
    const float* Wa   = (const float*)d_in[5];
    const float* Wb   = (const float*)d_in[6];
    const float* Wql  = (const float*)d_in[7];
    const float* Wqr  = (const float*)d_in[8];
    const float* Wsd  = (const float*)d_in[9];
    const float* bsd  = (const float*)d_in[10];
    const float* Wpd  = (const float*)d_in[11];
    const float* bpd  = (const float*)d_in[12];
    const float* Wout = (const float*)d_in[13];
    const float* W1   = (const float*)d_in[14];
    const float* b1   = (const float*)d_in[15];
    const float* W2   = (const float*)d_in[16];
    const float* b2   = (const float*)d_in[17];
    float* out = (float*)d_out;

    float *pn, *pa, *pb, *pql, *pqr, *psd, *ppd, *pg, *pr, *pl2, *ph;
    cudaGetSymbolAddress((void**)&pn,  g_n);
    cudaGetSymbolAddress((void**)&pa,  g_a);
    cudaGetSymbolAddress((void**)&pb,  g_b);
    cudaGetSymbolAddress((void**)&pql, g_ql);
    cudaGetSymbolAddress((void**)&pqr, g_qr);
    cudaGetSymbolAddress((void**)&psd, g_sd);
    cudaGetSymbolAddress((void**)&ppd, g_pd);
    cudaGetSymbolAddress((void**)&pg,  g_g);
    cudaGetSymbolAddress((void**)&pr,  g_r);
    cudaGetSymbolAddress((void**)&pl2, g_l2);
    cudaGetSymbolAddress((void**)&ph,  g_h);

    // 1) n = LN(x)
    ln_kernel<<<MROWS, 128>>>(x, ng, nb, pn);

    // 2) tanh projections a,b,ql,qr  (M=16384, N=512, K=512)
    dim3 gp(INNER / 128, MROWS / 128);
    sgemm_kernel<EPI_TANH><<<gp, 256>>>(pn, Wa,  nullptr, nullptr, pa,  INNER, DMdim);
    sgemm_kernel<EPI_TANH><<<gp, 256>>>(pn, Wb,  nullptr, nullptr, pb,  INNER, DMdim);
    sgemm_kernel<EPI_TANH><<<gp, 256>>>(pn, Wql, nullptr, nullptr, pql, INNER, DMdim);
    sgemm_kernel<EPI_TANH><<<gp, 256>>>(pn, Wqr, nullptr, nullptr, pqr, INNER, DMdim);

    // 3) sigmoid gates sd, pd
    sdpd_kernel<<<MROWS, 512>>>(pn, Wsd, bsd, Wpd, bpd, psd, ppd);

    // 4) sequential pair-state scan -> g = lc * qr
    pair_scan_kernel<<<128, 256>>>(pa, pb, pql, pqr, psd, ppd, pg);

    // 5) r = x + g @ Wout^T
    sgemm_kernel<EPI_RES><<<dim3(DMdim / 128, MROWS / 128), 256>>>(
        pg, Wout, nullptr, x, pr, DMdim, INNER);

    // 6) ln2 = LN(r)
    ln_kernel<<<MROWS, 128>>>(pr, fng, fnb, pl2);

    // 7) h = gelu(ln2 @ W1^T + b1)   (N=2048, K=512)
    sgemm_kernel<EPI_BIAS_GELU><<<dim3(HID / 128, MROWS / 128), 256>>>(
        pl2, W1, b1, nullptr, ph, HID, DMdim);

    // 8) out = r + h @ W2^T + b2     (N=512, K=2048)
    sgemm_kernel<EPI_BIAS_RES><<<dim3(DMdim / 128, MROWS / 128), 256>>>(
        ph, W2, b2, pr, out, DMdim, HID);
}

// round 2
// speedup vs baseline: 1.7285x; 1.7285x over previous
#include <cuda_runtime.h>
#include <math.h>

// Problem dims
#define Bsz   8
#define Ssz   2048
#define DMdim 512
#define Hh    8
#define SDdim 64
#define INNER 512
#define HID   2048
#define MROWS (Bsz*Ssz)   // 16384

// ---------------- scratch (device globals: allocation-free) ----------------
__device__ float g_n [MROWS*DMdim];
__device__ float g_a [MROWS*INNER];
__device__ float g_b [MROWS*INNER];
__device__ float g_ql[MROWS*INNER];
__device__ float g_qr[MROWS*INNER];
__device__ float g_sd[MROWS*Hh];
__device__ float g_pd[MROWS*Hh];
__device__ float g_g [MROWS*INNER];
__device__ float g_r [MROWS*DMdim];
__device__ float g_l2[MROWS*DMdim];
__device__ float g_h [MROWS*HID];

// ---------------- LayerNorm ----------------
__global__ __launch_bounds__(128)
void ln_kernel(const float* __restrict__ x, const float* __restrict__ gm,
               const float* __restrict__ bt, float* __restrict__ out)
{
    int row = blockIdx.x;
    int tid = threadIdx.x;
    const float4* xr = (const float4*)(x + (size_t)row * DMdim);
    float4 v = xr[tid];
    float s  = v.x + v.y + v.z + v.w;
    float s2 = v.x*v.x + v.y*v.y + v.z*v.z + v.w*v.w;
    #pragma unroll
    for (int o = 16; o > 0; o >>= 1) {
        s  += __shfl_xor_sync(0xffffffffu, s,  o);
        s2 += __shfl_xor_sync(0xffffffffu, s2, o);
    }
    __shared__ float ss[4], ss2[4];
    int wid = tid >> 5, lane = tid & 31;
    if (lane == 0) { ss[wid] = s; ss2[wid] = s2; }
    __syncthreads();
    s  = ss[0] + ss[1] + ss[2] + ss[3];
    s2 = ss2[0] + ss2[1] + ss2[2] + ss2[3];
    float m   = s * (1.0f / DMdim);
    float var = s2 * (1.0f / DMdim) - m * m;
    float inv = rsqrtf(var + 1e-5f);
    float4 gv = ((const float4*)gm)[tid];
    float4 bv = ((const float4*)bt)[tid];
    float4 o;
    o.x = (v.x - m) * inv * gv.x + bv.x;
    o.y = (v.y - m) * inv * gv.y + bv.y;
    o.z = (v.z - m) * inv * gv.z + bv.z;
    o.w = (v.w - m) * inv * gv.w + bv.w;
    ((float4*)(out + (size_t)row * DMdim))[tid] = o;
}

// ---------------- sd/pd gates ----------------
__global__ __launch_bounds__(512)
void sdpd_kernel(const float* __restrict__ n,
                 const float* __restrict__ Wsd, const float* __restrict__ bsd,
                 const float* __restrict__ Wpd, const float* __restrict__ bpd,
                 float* __restrict__ sd, float* __restrict__ pd)
{
    int row = blockIdx.x;
    __shared__ float nr[DMdim];
    int tid = threadIdx.x;
    nr[tid] = n[(size_t)row * DMdim + tid];
    __syncthreads();
    int w = tid >> 5, lane = tid & 31;
    const float* Wt = (w < 8) ? (Wsd + (size_t)w * DMdim) : (Wpd + (size_t)(w - 8) * DMdim);
    float acc = 0.f;
    #pragma unroll
    for (int j = lane; j < DMdim; j += 32) acc += nr[j] * Wt[j];
    #pragma unroll
    for (int o = 16; o > 0; o >>= 1) acc += __shfl_xor_sync(0xffffffffu, acc, o);
    if (lane == 0) {
        int h = w & 7;
        float bias = (w < 8) ? bsd[h] : bpd[h];
        float v = 1.f / (1.f + expf(-(acc + bias)));
        if (w < 8) sd[(size_t)row * Hh + h] = v;
        else       pd[(size_t)row * Hh + h] = v;
    }
}

// ---------------- tf32 tensor-core GEMM ----------------
// C[M,N] = A[M,K] @ B[N,K]^T. Both operands K-contiguous (row.col mma layout).
// BM=BN=128, BK=16, 256 threads, 8 warps (4m x 2n), warp tile 32x64.
enum { EPI_TANH = 0, EPI_RES = 1, EPI_BIAS_GELU = 2, EPI_BIAS_RES = 3 };

__device__ __forceinline__ unsigned f2tf32(float x) {
    unsigned r;
    asm("cvt.rna.tf32.f32 %0, %1;" : "=r"(r) : "f"(x));
    return r;
}

template<int EPI>
__global__ __launch_bounds__(256)
void mma_gemm_kernel(const float* __restrict__ A, const float* __restrict__ Bw,
                     const float* __restrict__ bias, const float* __restrict__ resid,
                     float* __restrict__ C, int N, int K)
{
    const int BM = 128, BN = 128, BK = 16;
    __shared__ unsigned As[BK][BM + 4];
    __shared__ unsigned Bs[BK][BN + 4];
    int tid  = threadIdx.x;
    int warp = tid >> 5, lane = tid & 31;
    int gq = lane >> 2, tg = lane & 3;      // group, thread-in-group
    int wm = warp & 3, wn = warp >> 2;      // 4 x 2 warp grid
    int bn0 = blockIdx.x * BN, bm0 = blockIdx.y * BM;

    float acc[2][8][4];
    #pragma unroll
    for (int i = 0; i < 2; i++)
        #pragma unroll
        for (int j = 0; j < 8; j++)
            #pragma unroll
            for (int q = 0; q < 4; q++) acc[i][j][q] = 0.f;

    float4 ra[2], rb[2];
    auto LOADG = [&](int k0) {
        #pragma unroll
        for (int c = 0; c < 2; c++) {
            int idx = tid + c * 256;
            int m  = idx >> 2;
            int kk = (idx & 3) << 2;
            ra[c] = *(const float4*)(A  + (size_t)(bm0 + m) * K + k0 + kk);
            rb[c] = *(const float4*)(Bw + (size_t)(bn0 + m) * K + k0 + kk);
        }
    };
    auto STORES = [&]() {
        #pragma unroll
        for (int c = 0; c < 2; c++) {
            int idx = tid + c * 256;
            int m  = idx >> 2;
            int kk = (idx & 3) << 2;
            As[kk+0][m] = f2tf32(ra[c].x); As[kk+1][m] = f2tf32(ra[c].y);
            As[kk+2][m] = f2tf32(ra[c].z); As[kk+3][m] = f2tf32(ra[c].w);
            Bs[kk+0][m] = f2tf32(rb[c].x); Bs[kk+1][m] = f2tf32(rb[c].y);
            Bs[kk+2][m] = f2tf32(rb[c].z); Bs[kk+3][m] = f2tf32(rb[c].w);
        }
    };

    LOADG(0);
    STORES();
    __syncthreads();

    for (int k0 = 0; k0 < K; k0 += BK) {
        bool more = (k0 + BK) < K;
        if (more) LOADG(k0 + BK);

        #pragma unroll
        for (int ks = 0; ks < BK; ks += 8) {
            unsigned af[2][4], bf[8][2];
            #pragma unroll
            for (int i = 0; i < 2; i++) {
                int m0 = wm * 32 + i * 16;
                af[i][0] = As[ks + tg    ][m0 + gq    ];
                af[i][1] = As[ks + tg    ][m0 + gq + 8];
                af[i][2] = As[ks + tg + 4][m0 + gq    ];
                af[i][3] = As[ks + tg + 4][m0 + gq + 8];
            }
            #pragma unroll
            for (int j = 0; j < 8; j++) {
                int n0 = wn * 64 + j * 8;
                bf[j][0] = Bs[ks + tg    ][n0 + gq];
                bf[j][1] = Bs[ks + tg + 4][n0 + gq];
            }
            #pragma unroll
            for (int i = 0; i < 2; i++)
                #pragma unroll
                for (int j = 0; j < 8; j++) {
                    asm volatile(
                        "mma.sync.aligned.m16n8k8.row.col.f32.tf32.tf32.f32 "
                        "{%0,%1,%2,%3}, {%4,%5,%6,%7}, {%8,%9}, {%0,%1,%2,%3};"
                        : "+f"(acc[i][j][0]), "+f"(acc[i][j][1]),
                          "+f"(acc[i][j][2]), "+f"(acc[i][j][3])
                        : "r"(af[i][0]), "r"(af[i][1]), "r"(af[i][2]), "r"(af[i][3]),
                          "r"(bf[j][0]), "r"(bf[j][1]));
                }
        }
        __syncthreads();
        if (more) { STORES(); __syncthreads(); }
    }

    // epilogue: thread holds (rows {r0, r0+8}) x (cols {c0, c0+1}) per tile
    #pragma unroll
    for (int i = 0; i < 2; i++) {
        int r0 = bm0 + wm * 32 + i * 16 + gq;
        #pragma unroll
        for (int j = 0; j < 8; j++) {
            int col = bn0 + wn * 64 + j * 8 + tg * 2;
            #pragma unroll
            for (int half = 0; half < 2; half++) {
                int row = r0 + half * 8;
                float v0 = acc[i][j][half * 2 + 0];
                float v1 = acc[i][j][half * 2 + 1];
                if (EPI == EPI_BIAS_GELU || EPI == EPI_BIAS_RES) {
                    v0 += bias[col]; v1 += bias[col + 1];
                }
                if (EPI == EPI_TANH) { v0 = tanhf(v0); v1 = tanhf(v1); }
                if (EPI == EPI_BIAS_GELU) {
                    v0 = 0.5f * v0 * (1.f + erff(v0 * 0.70710678118654752f));
                    v1 = 0.5f * v1 * (1.f + erff(v1 * 0.70710678118654752f));
                }
                if (EPI == EPI_RES || EPI == EPI_BIAS_RES) {
                    float2 rv = *(const float2*)(resid + (size_t)row * N + col);
                    v0 += rv.x; v1 += rv.y;
                }
                float2 o = {v0, v1};
                *(float2*)(C + (size_t)row * N + col) = o;
            }
        }
    }
}

// ---------------- pair-state scan: register-resident, no barriers ----------------
// grid = 128 blocks: (b,h) x 2 e-halves. 256 threads: el = tid>>3 (32 e vals),
// dq = tid&7 (8 d-slices of 8). Thread owns pair[dq*8+i][e] in regs and a
// redundant copy of state[dq*8+i]. Next-step inputs prefetched into regs.
__global__ __launch_bounds__(256)
void pair_scan_kernel(const float* __restrict__ a,  const float* __restrict__ bm,
                      const float* __restrict__ ql, const float* __restrict__ qr,
                      const float* __restrict__ sd, const float* __restrict__ pd,
                      float* __restrict__ g)
{
    int blk = blockIdx.x;
    int eh  = blk & 1;
    int bh  = blk >> 1;
    int tid = threadIdx.x;
    int el  = tid >> 3;
    int dq  = tid & 7;
    int e   = eh * 32 + el;

    size_t base  = (size_t)(bh >> 3) * Ssz * INNER + (size_t)(bh & 7) * SDdim;
    size_t base8 = (size_t)(bh >> 3) * Ssz * Hh + (bh & 7);

    float p[8], st[8];
    #pragma unroll
    for (int i = 0; i < 8; i++) { p[i] = 0.f; st[i] = 0.f; }

    float4 a0, a1, q0, q1;
    float bv, qrv, sdv, pdv;

    auto LOAD = [&](size_t bs, size_t b8, float4& A0, float4& A1,
                    float4& Q0, float4& Q1, float& BV, float& QRV,
                    float& SDV, float& PDV) {
        const float4* ap = (const float4*)(a  + bs + dq * 8);
        const float4* qp = (const float4*)(ql + bs + dq * 8);
        A0 = ap[0]; A1 = ap[1];
        Q0 = qp[0]; Q1 = qp[1];
        BV  = bm[bs + e];
        QRV = qr[bs + e];
        SDV = sd[b8];
        PDV = pd[b8];
    };

    LOAD(base, base8, a0, a1, q0, q1, bv, qrv, sdv, pdv);

    for (int t = 0; t < Ssz; t++) {
        float4 na0 = {0,0,0,0}, na1 = {0,0,0,0}, nq0 = {0,0,0,0}, nq1 = {0,0,0,0};
        float nbv = 0.f, nqrv = 0.f, nsdv = 0.f, npdv = 0.f;
        size_t nb  = base + INNER;
        size_t nb8 = base8 + Hh;
        if (t + 1 < Ssz)
            LOAD(nb, nb8, na0, na1, nq0, nq1, nbv, nqrv, nsdv, npdv);

        float c = (1.f - pdv) * bv;
        float av[8] = {a0.x, a0.y, a0.z, a0.w, a1.x, a1.y, a1.z, a1.w};
        float qv[8] = {q0.x, q0.y, q0.z, q0.w, q1.x, q1.y, q1.z, q1.w};

        float lacc = 0.f;
        #pragma unroll
        for (int i = 0; i < 8; i++) {
            p[i] = pdv * p[i] + c * st[i];   // uses prev state
            lacc += p[i] * qv[i];
        }
        #pragma unroll
        for (int i = 0; i < 8; i++)
            st[i] = sdv * st[i] + (1.f - sdv) * av[i];

        lacc += __shfl_xor_sync(0xffffffffu, lacc, 1);
        lacc += __shfl_xor_sync(0xffffffffu, lacc, 2);
        lacc += __shfl_xor_sync(0xffffffffu, lacc, 4);
        if (dq == 0) g[base + e] = lacc * qrv;

        a0 = na0; a1 = na1; q0 = nq0; q1 = nq1;
        bv = nbv; qrv = nqrv; sdv = nsdv; pdv = npdv;
        base = nb; base8 = nb8;
    }
}

// ---------------- launch ----------------
extern "C" void kernel_launch(void* const* d_in, const int* in_sizes, int n_in,
                              void* d_out, int out_size)
{
    const float* x    = (const float*)d_in[0];
    const float* ng   = (const float*)d_in[1];
    const float* nb   = (const float*)d_in[2];
    const float* fng  = (const float*)d_in[3];
    const float* fnb  = (const float*)d_in[4];
    const float* Wa   = (const float*)d_in[5];
    const float* Wb   = (const float*)d_in[6];
    const float* Wql  = (const float*)d_in[7];
    const float* Wqr  = (const float*)d_in[8];
    const float* Wsd  = (const float*)d_in[9];
    const float* bsd  = (const float*)d_in[10];
    const float* Wpd  = (const float*)d_in[11];
    const float* bpd  = (const float*)d_in[12];
    const float* Wout = (const float*)d_in[13];
    const float* W1   = (const float*)d_in[14];
    const float* b1   = (const float*)d_in[15];
    const float* W2   = (const float*)d_in[16];
    const float* b2   = (const float*)d_in[17];
    float* out = (float*)d_out;

    float *pn, *pa, *pb, *pql, *pqr, *psd, *ppd, *pg, *pr, *pl2, *ph;
    cudaGetSymbolAddress((void**)&pn,  g_n);
    cudaGetSymbolAddress((void**)&pa,  g_a);
    cudaGetSymbolAddress((void**)&pb,  g_b);
    cudaGetSymbolAddress((void**)&pql, g_ql);
    cudaGetSymbolAddress((void**)&pqr, g_qr);
    cudaGetSymbolAddress((void**)&psd, g_sd);
    cudaGetSymbolAddress((void**)&ppd, g_pd);
    cudaGetSymbolAddress((void**)&pg,  g_g);
    cudaGetSymbolAddress((void**)&pr,  g_r);
    cudaGetSymbolAddress((void**)&pl2, g_l2);
    cudaGetSymbolAddress((void**)&ph,  g_h);

    // 1) n = LN(x)
    ln_kernel<<<MROWS, 128>>>(x, ng, nb, pn);

    // 2) tanh projections (M=16384, N=512, K=512) on tensor cores
    dim3 gp(INNER / 128, MROWS / 128);
    mma_gemm_kernel<EPI_TANH><<<gp, 256>>>(pn, Wa,  nullptr, nullptr, pa,  INNER, DMdim);
    mma_gemm_kernel<EPI_TANH><<<gp, 256>>>(pn, Wb,  nullptr, nullptr, pb,  INNER, DMdim);
    mma_gemm_kernel<EPI_TANH><<<gp, 256>>>(pn, Wql, nullptr, nullptr, pql, INNER, DMdim);
    mma_gemm_kernel<EPI_TANH><<<gp, 256>>>(pn, Wqr, nullptr, nullptr, pqr, INNER, DMdim);

    // 3) sigmoid gates
    sdpd_kernel<<<MROWS, 512>>>(pn, Wsd, bsd, Wpd, bpd, psd, ppd);

    // 4) pair-state scan -> g = lc * qr
    pair_scan_kernel<<<128, 256>>>(pa, pb, pql, pqr, psd, ppd, pg);

    // 5) r = x + g @ Wout^T
    mma_gemm_kernel<EPI_RES><<<dim3(DMdim / 128, MROWS / 128), 256>>>(
        pg, Wout, nullptr, x, pr, DMdim, INNER);

    // 6) ln2 = LN(r)
    ln_kernel<<<MROWS, 128>>>(pr, fng, fnb, pl2);

    // 7) h = gelu(ln2 @ W1^T + b1)
    mma_gemm_kernel<EPI_BIAS_GELU><<<dim3(HID / 128, MROWS / 128), 256>>>(
        pl2, W1, b1, nullptr, ph, HID, DMdim);

    // 8) out = r + h @ W2^T + b2
    mma_gemm_kernel<EPI_BIAS_RES><<<dim3(DMdim / 128, MROWS / 128), 256>>>(
        ph, W2, b2, pr, out, DMdim, HID);
}

// round 3
// speedup vs baseline: 2.8401x; 1.6431x over previous
#include <cuda_runtime.h>
#include <math.h>

// Problem dims
#define Bsz   8
#define Ssz   2048
#define DMdim 512
#define Hh    8
#define SDdim 64
#define INNER 512
#define HID   2048
#define MROWS (Bsz*Ssz)   // 16384

// ---------------- scratch (device globals: allocation-free) ----------------
__device__ float g_n [MROWS*DMdim];
__device__ float g_a [MROWS*INNER];
__device__ float g_b [MROWS*INNER];
__device__ float g_ql[MROWS*INNER];
__device__ float g_qr[MROWS*INNER];
__device__ float g_sd[MROWS*Hh];
__device__ float g_pd[MROWS*Hh];
__device__ float g_g [MROWS*INNER];
__device__ float g_r [MROWS*DMdim];
__device__ float g_l2[MROWS*DMdim];
__device__ float g_h [MROWS*HID];

// ---------------- LayerNorm ----------------
__global__ __launch_bounds__(128)
void ln_kernel(const float* __restrict__ x, const float* __restrict__ gm,
               const float* __restrict__ bt, float* __restrict__ out)
{
    int row = blockIdx.x;
    int tid = threadIdx.x;
    const float4* xr = (const float4*)(x + (size_t)row * DMdim);
    float4 v = xr[tid];
    float s  = v.x + v.y + v.z + v.w;
    float s2 = v.x*v.x + v.y*v.y + v.z*v.z + v.w*v.w;
    #pragma unroll
    for (int o = 16; o > 0; o >>= 1) {
        s  += __shfl_xor_sync(0xffffffffu, s,  o);
        s2 += __shfl_xor_sync(0xffffffffu, s2, o);
    }
    __shared__ float ss[4], ss2[4];
    int wid = tid >> 5, lane = tid & 31;
    if (lane == 0) { ss[wid] = s; ss2[wid] = s2; }
    __syncthreads();
    s  = ss[0] + ss[1] + ss[2] + ss[3];
    s2 = ss2[0] + ss2[1] + ss2[2] + ss2[3];
    float m   = s * (1.0f / DMdim);
    float var = s2 * (1.0f / DMdim) - m * m;
    float inv = rsqrtf(var + 1e-5f);
    float4 gv = ((const float4*)gm)[tid];
    float4 bv = ((const float4*)bt)[tid];
    float4 o;
    o.x = (v.x - m) * inv * gv.x + bv.x;
    o.y = (v.y - m) * inv * gv.y + bv.y;
    o.z = (v.z - m) * inv * gv.z + bv.z;
    o.w = (v.w - m) * inv * gv.w + bv.w;
    ((float4*)(out + (size_t)row * DMdim))[tid] = o;
}

// ---------------- sd/pd gates ----------------
__global__ __launch_bounds__(512)
void sdpd_kernel(const float* __restrict__ n,
                 const float* __restrict__ Wsd, const float* __restrict__ bsd,
                 const float* __restrict__ Wpd, const float* __restrict__ bpd,
                 float* __restrict__ sd, float* __restrict__ pd)
{
    int row = blockIdx.x;
    __shared__ float nr[DMdim];
    int tid = threadIdx.x;
    nr[tid] = n[(size_t)row * DMdim + tid];
    __syncthreads();
    int w = tid >> 5, lane = tid & 31;
    const float* Wt = (w < 8) ? (Wsd + (size_t)w * DMdim) : (Wpd + (size_t)(w - 8) * DMdim);
    float acc = 0.f;
    #pragma unroll
    for (int j = lane; j < DMdim; j += 32) acc += nr[j] * Wt[j];
    #pragma unroll
    for (int o = 16; o > 0; o >>= 1) acc += __shfl_xor_sync(0xffffffffu, acc, o);
    if (lane == 0) {
        int h = w & 7;
        float bias = (w < 8) ? bsd[h] : bpd[h];
        float v = 1.f / (1.f + expf(-(acc + bias)));
        if (w < 8) sd[(size_t)row * Hh + h] = v;
        else       pd[(size_t)row * Hh + h] = v;
    }
}

// ---------------- tf32 tensor-core GEMM ----------------
// C[M,N] = A[M,K] @ B[N,K]^T. BM=BN=128, BK=16, 256 threads, 8 warps (4m x 2n).
// Double-buffered smem, pair-interleaved k layout so fragment loads are LDS.64
// fetching the (k, k+4) pair each mma needs.
enum { EPI_TANH = 0, EPI_RES = 1, EPI_BIAS_GELU = 2, EPI_BIAS_RES = 3 };

__device__ __forceinline__ unsigned f2tf32(float x) {
    unsigned r;
    asm("cvt.rna.tf32.f32 %0, %1;" : "=r"(r) : "f"(x));
    return r;
}

template<int EPI>
__global__ __launch_bounds__(256)
void mma_gemm_kernel(const float* __restrict__ A, const float* __restrict__ Bw,
                     const float* __restrict__ bias, const float* __restrict__ resid,
                     float* __restrict__ C, int N, int K)
{
    const int BM = 128, BN = 128, BK = 16;
    // slot(k) = (k&8) | ((k&3)*2) | ((k>>2)&1)  -> (tg, tg+4) adjacent
    __shared__ unsigned As[2][BM][18];
    __shared__ unsigned Bs[2][BN][18];
    int tid  = threadIdx.x;
    int warp = tid >> 5, lane = tid & 31;
    int gq = lane >> 2, tg = lane & 3;
    int wm = warp & 3, wn = warp >> 2;
    int bn0 = blockIdx.x * BN, bm0 = blockIdx.y * BM;

    float acc[2][8][4];
    #pragma unroll
    for (int i = 0; i < 2; i++)
        #pragma unroll
        for (int j = 0; j < 8; j++)
            #pragma unroll
            for (int q = 0; q < 4; q++) acc[i][j][q] = 0.f;

    float4 ra[2], rb[2];
    auto LOADG = [&](int k0) {
        #pragma unroll
        for (int c = 0; c < 2; c++) {
            int idx = tid + c * 256;
            int m  = idx >> 2;
            int kk = (idx & 3) << 2;
            ra[c] = *(const float4*)(A  + (size_t)(bm0 + m) * K + k0 + kk);
            rb[c] = *(const float4*)(Bw + (size_t)(bn0 + m) * K + k0 + kk);
        }
    };
    auto STORES = [&](int bf) {
        #pragma unroll
        for (int c = 0; c < 2; c++) {
            int idx = tid + c * 256;
            int m  = idx >> 2;
            int kk = (idx & 3) << 2;
            int s0 = (kk & 8) | ((kk >> 2) & 1);
            As[bf][m][s0 + 0] = f2tf32(ra[c].x);
            As[bf][m][s0 + 2] = f2tf32(ra[c].y);
            As[bf][m][s0 + 4] = f2tf32(ra[c].z);
            As[bf][m][s0 + 6] = f2tf32(ra[c].w);
            Bs[bf][m][s0 + 0] = f2tf32(rb[c].x);
            Bs[bf][m][s0 + 2] = f2tf32(rb[c].y);
            Bs[bf][m][s0 + 4] = f2tf32(rb[c].z);
            Bs[bf][m][s0 + 6] = f2tf32(rb[c].w);
        }
    };

    LOADG(0);
    STORES(0);
    __syncthreads();

    int buf = 0;
    for (int k0 = 0; k0 < K; k0 += BK) {
        bool more = (k0 + BK) < K;
        if (more) LOADG(k0 + BK);

        #pragma unroll
        for (int s = 0; s < 2; s++) {
            int s8 = s * 8 + tg * 2;
            uint2 a0p[2], a1p[2];
            #pragma unroll
            for (int i = 0; i < 2; i++) {
                int m0 = wm * 32 + i * 16;
                a0p[i] = *(const uint2*)&As[buf][m0 + gq    ][s8];
                a1p[i] = *(const uint2*)&As[buf][m0 + gq + 8][s8];
            }
            uint2 bp[8];
            #pragma unroll
            for (int j = 0; j < 8; j++)
                bp[j] = *(const uint2*)&Bs[buf][wn * 64 + j * 8 + gq][s8];
            #pragma unroll
            for (int i = 0; i < 2; i++)
                #pragma unroll
                for (int j = 0; j < 8; j++) {
                    asm volatile(
                        "mma.sync.aligned.m16n8k8.row.col.f32.tf32.tf32.f32 "
                        "{%0,%1,%2,%3}, {%4,%5,%6,%7}, {%8,%9}, {%0,%1,%2,%3};"
                        : "+f"(acc[i][j][0]), "+f"(acc[i][j][1]),
                          "+f"(acc[i][j][2]), "+f"(acc[i][j][3])
                        : "r"(a0p[i].x), "r"(a1p[i].x), "r"(a0p[i].y), "r"(a1p[i].y),
                          "r"(bp[j].x), "r"(bp[j].y));
                }
        }
        if (more) STORES(buf ^ 1);
        __syncthreads();
        buf ^= 1;
    }

    #pragma unroll
    for (int i = 0; i < 2; i++) {
        int r0 = bm0 + wm * 32 + i * 16 + gq;
        #pragma unroll
        for (int j = 0; j < 8; j++) {
            int col = bn0 + wn * 64 + j * 8 + tg * 2;
            #pragma unroll
            for (int half = 0; half < 2; half++) {
                int row = r0 + half * 8;
                float v0 = acc[i][j][half * 2 + 0];
                float v1 = acc[i][j][half * 2 + 1];
                if (EPI == EPI_BIAS_GELU || EPI == EPI_BIAS_RES) {
                    v0 += bias[col]; v1 += bias[col + 1];
                }
                if (EPI == EPI_TANH) { v0 = tanhf(v0); v1 = tanhf(v1); }
                if (EPI == EPI_BIAS_GELU) {
                    v0 = 0.5f * v0 * (1.f + erff(v0 * 0.70710678118654752f));
                    v1 = 0.5f * v1 * (1.f + erff(v1 * 0.70710678118654752f));
                }
                if (EPI == EPI_RES || EPI == EPI_BIAS_RES) {
                    float2 rv = *(const float2*)(resid + (size_t)row * N + col);
                    v0 += rv.x; v1 += rv.y;
                }
                float2 o = {v0, v1};
                *(float2*)(C + (size_t)row * N + col) = o;
            }
        }
    }
}

// ---------------- pair-state scan: chunked smem pipeline ----------------
// grid 128: (b,h) x 2 e-halves. 256 threads: el = tid>>3 (32), dq = tid&7.
// Thread owns pair[dq*8+i][e] and a redundant state slice st[dq*8+i] in regs.
// CHUNK=16 steps staged through double-buffered smem; one barrier per chunk.
#define SCHUNK 16
__global__ __launch_bounds__(256)
void pair_scan_kernel(const float* __restrict__ a,  const float* __restrict__ bm,
                      const float* __restrict__ ql, const float* __restrict__ qr,
                      const float* __restrict__ sd, const float* __restrict__ pd,
                      float* __restrict__ g)
{
    int blk = blockIdx.x;
    int eh  = blk & 1;
    int bh  = blk >> 1;
    int tid = threadIdx.x;
    int el  = tid >> 3;
    int dq  = tid & 7;

    __shared__ float sa [2][SCHUNK][64];
    __shared__ float sq [2][SCHUNK][64];
    __shared__ float sbh[2][SCHUNK][32];
    __shared__ float srh[2][SCHUNK][32];
    __shared__ float ssd[2][SCHUNK];
    __shared__ float spd[2][SCHUNK];

    size_t base0  = (size_t)(bh >> 3) * Ssz * INNER + (size_t)(bh & 7) * SDdim;
    size_t base80 = (size_t)(bh >> 3) * Ssz * Hh + (bh & 7);

    // per-thread load assignments
    int tA = tid >> 4, fA = tid & 15;          // a, ql : [16 t][16 float4]
    int tB = (tid & 127) >> 3, fB = tid & 7;   // b/qr halves : [16 t][8 float4]
    bool loB = tid < 128;                      // bm half
    bool loSd = tid < SCHUNK;                  // sd
    bool loPd = tid >= 32 && tid < 32 + SCHUNK;

    float4 rA, rQ, rH;
    float  rS = 0.f;

    auto LOADC = [&](int c) {
        size_t bs = base0 + (size_t)c * SCHUNK * INNER;
        size_t b8 = base80 + (size_t)c * SCHUNK * Hh;
        rA = *(const float4*)(a  + bs + (size_t)tA * INNER + fA * 4);
        rQ = *(const float4*)(ql + bs + (size_t)tA * INNER + fA * 4);
        const float* hsrc = loB ? bm : qr;
        rH = *(const float4*)(hsrc + bs + (size_t)tB * INNER + eh * 32 + fB * 4);
        if (loSd)      rS = sd[b8 + (size_t)tid * Hh];
        else if (loPd) rS = pd[b8 + (size_t)(tid - 32) * Hh];
    };
    auto STOREC = [&](int bf) {
        *(float4*)&sa[bf][tA][fA * 4] = rA;
        *(float4*)&sq[bf][tA][fA * 4] = rQ;
        if (loB) *(float4*)&sbh[bf][tB][fB * 4] = rH;
        else     *(float4*)&srh[bf][tB][fB * 4] = rH;
        if (loSd)      ssd[bf][tid]      = rS;
        else if (loPd) spd[bf][tid - 32] = rS;
    };

    float p[8], st[8];
    #pragma unroll
    for (int i = 0; i < 8; i++) { p[i] = 0.f; st[i] = 0.f; }

    LOADC(0);
    STOREC(0);
    __syncthreads();

    const int NC = Ssz / SCHUNK;
    int buf = 0;
    size_t gbase = base0 + eh * 32 + el;

    for (int c = 0; c < NC; c++) {
        bool more = (c + 1) < NC;
        if (more) LOADC(c + 1);

        #pragma unroll 4
        for (int t = 0; t < SCHUNK; t++) {
            float sdv = ssd[buf][t];
            float pdv = spd[buf][t];
            float cc  = (1.f - pdv) * sbh[buf][t][el];
            float4 q0 = *(const float4*)&sq[buf][t][dq * 8];
            float4 q1 = *(const float4*)&sq[buf][t][dq * 8 + 4];
            float4 a0 = *(const float4*)&sa[buf][t][dq * 8];
            float4 a1 = *(const float4*)&sa[buf][t][dq * 8 + 4];
            float qv[8] = {q0.x,q0.y,q0.z,q0.w,q1.x,q1.y,q1.z,q1.w};
            float av[8] = {a0.x,a0.y,a0.z,a0.w,a1.x,a1.y,a1.z,a1.w};

            float lacc = 0.f;
            #pragma unroll
            for (int i = 0; i < 8; i++) {
                p[i] = pdv * p[i] + cc * st[i];   // uses prev state
                lacc += p[i] * qv[i];
            }
            float om = 1.f - sdv;
            #pragma unroll
            for (int i = 0; i < 8; i++)
                st[i] = sdv * st[i] + om * av[i];

            lacc += __shfl_xor_sync(0xffffffffu, lacc, 1);
            lacc += __shfl_xor_sync(0xffffffffu, lacc, 2);
            lacc += __shfl_xor_sync(0xffffffffu, lacc, 4);
            if (dq == 0) g[gbase + (size_t)t * INNER] = lacc * srh[buf][t][el];
        }

        if (more) STOREC(buf ^ 1);
        __syncthreads();
        buf ^= 1;
        gbase += (size_t)SCHUNK * INNER;
    }
}

// ---------------- launch ----------------
extern "C" void kernel_launch(void* const* d_in, const int* in_sizes, int n_in,
                              void* d_out, int out_size)
{
    const float* x    = (const float*)d_in[0];
    const float* ng   = (const float*)d_in[1];
    const float* nb   = (const float*)d_in[2];
    const float* fng  = (const float*)d_in[3];
    const float* fnb  = (const float*)d_in[4];
    const float* Wa   = (const float*)d_in[5];
    const float* Wb   = (const float*)d_in[6];
    const float* Wql  = (const float*)d_in[7];
    const float* Wqr  = (const float*)d_in[8];
    const float* Wsd  = (const float*)d_in[9];
    const float* bsd  = (const float*)d_in[10];
    const float* Wpd  = (const float*)d_in[11];
    const float* bpd  = (const float*)d_in[12];
    const float* Wout = (const float*)d_in[13];
    const float* W1   = (const float*)d_in[14];
    const float* b1   = (const float*)d_in[15];
    const float* W2   = (const float*)d_in[16];
    const float* b2   = (const float*)d_in[17];
    float* out = (float*)d_out;

    float *pn, *pa, *pb, *pql, *pqr, *psd, *ppd, *pg, *pr, *pl2, *ph;
    cudaGetSymbolAddress((void**)&pn,  g_n);
    cudaGetSymbolAddress((void**)&pa,  g_a);
    cudaGetSymbolAddress((void**)&pb,  g_b);
    cudaGetSymbolAddress((void**)&pql, g_ql);
    cudaGetSymbolAddress((void**)&pqr, g_qr);
    cudaGetSymbolAddress((void**)&psd, g_sd);
    cudaGetSymbolAddress((void**)&ppd, g_pd);
    cudaGetSymbolAddress((void**)&pg,  g_g);
    cudaGetSymbolAddress((void**)&pr,  g_r);
    cudaGetSymbolAddress((void**)&pl2, g_l2);
    cudaGetSymbolAddress((void**)&ph,  g_h);

    // 1) n = LN(x)
    ln_kernel<<<MROWS, 128>>>(x, ng, nb, pn);

    // 2) tanh projections (M=16384, N=512, K=512) on tensor cores
    dim3 gp(INNER / 128, MROWS / 128);
    mma_gemm_kernel<EPI_TANH><<<gp, 256>>>(pn, Wa,  nullptr, nullptr, pa,  INNER, DMdim);
    mma_gemm_kernel<EPI_TANH><<<gp, 256>>>(pn, Wb,  nullptr, nullptr, pb,  INNER, DMdim);
    mma_gemm_kernel<EPI_TANH><<<gp, 256>>>(pn, Wql, nullptr, nullptr, pql, INNER, DMdim);
    mma_gemm_kernel<EPI_TANH><<<gp, 256>>>(pn, Wqr, nullptr, nullptr, pqr, INNER, DMdim);

    // 3) sigmoid gates
    sdpd_kernel<<<MROWS, 512>>>(pn, Wsd, bsd, Wpd, bpd, psd, ppd);

    // 4) pair-state scan -> g = lc * qr
    pair_scan_kernel<<<128, 256>>>(pa, pb, pql, pqr, psd, ppd, pg);

    // 5) r = x + g @ Wout^T
    mma_gemm_kernel<EPI_RES><<<dim3(DMdim / 128, MROWS / 128), 256>>>(
        pg, Wout, nullptr, x, pr, DMdim, INNER);

    // 6) ln2 = LN(r)
    ln_kernel<<<MROWS, 128>>>(pr, fng, fnb, pl2);

    // 7) h = gelu(ln2 @ W1^T + b1)
    mma_gemm_kernel<EPI_BIAS_GELU><<<dim3(HID / 128, MROWS / 128), 256>>>(
        pl2, W1, b1, nullptr, ph, HID, DMdim);

    // 8) out = r + h @ W2^T + b2
    mma_gemm_kernel<EPI_BIAS_RES><<<dim3(DMdim / 128, MROWS / 128), 256>>>(
        ph, W2, b2, pr, out, DMdim, HID);
}

// round 4
// speedup vs baseline: 3.7367x; 1.3157x over previous
#include <cuda_runtime.h>
#include <math.h>

// Problem dims
#define Bsz   8
#define Ssz   2048
#define DMdim 512
#define Hh    8
#define SDdim 64
#define INNER 512
#define HID   2048
#define MROWS (Bsz*Ssz)   // 16384

// ---------------- scratch (device globals: allocation-free) ----------------
__device__ float g_n [MROWS*DMdim];
__device__ float g_a [MROWS*INNER];
__device__ float g_b [MROWS*INNER];
__device__ float g_ql[MROWS*INNER];
__device__ float g_qr[MROWS*INNER];
__device__ float g_sd[MROWS*Hh];
__device__ float g_pd[MROWS*Hh];
__device__ float g_g [MROWS*INNER];
__device__ float g_r [MROWS*DMdim];
__device__ float g_l2[MROWS*DMdim];
__device__ float g_h [MROWS*HID];

// ---------------- LayerNorm ----------------
__global__ __launch_bounds__(128)
void ln_kernel(const float* __restrict__ x, const float* __restrict__ gm,
               const float* __restrict__ bt, float* __restrict__ out)
{
    int row = blockIdx.x;
    int tid = threadIdx.x;
    const float4* xr = (const float4*)(x + (size_t)row * DMdim);
    float4 v = xr[tid];
    float s  = v.x + v.y + v.z + v.w;
    float s2 = v.x*v.x + v.y*v.y + v.z*v.z + v.w*v.w;
    #pragma unroll
    for (int o = 16; o > 0; o >>= 1) {
        s  += __shfl_xor_sync(0xffffffffu, s,  o);
        s2 += __shfl_xor_sync(0xffffffffu, s2, o);
    }
    __shared__ float ss[4], ss2[4];
    int wid = tid >> 5, lane = tid & 31;
    if (lane == 0) { ss[wid] = s; ss2[wid] = s2; }
    __syncthreads();
    s  = ss[0] + ss[1] + ss[2] + ss[3];
    s2 = ss2[0] + ss2[1] + ss2[2] + ss2[3];
    float m   = s * (1.0f / DMdim);
    float var = s2 * (1.0f / DMdim) - m * m;
    float inv = rsqrtf(var + 1e-5f);
    float4 gv = ((const float4*)gm)[tid];
    float4 bv = ((const float4*)bt)[tid];
    float4 o;
    o.x = (v.x - m) * inv * gv.x + bv.x;
    o.y = (v.y - m) * inv * gv.y + bv.y;
    o.z = (v.z - m) * inv * gv.z + bv.z;
    o.w = (v.w - m) * inv * gv.w + bv.w;
    ((float4*)(out + (size_t)row * DMdim))[tid] = o;
}

// ---------------- sd/pd gates ----------------
__global__ __launch_bounds__(512)
void sdpd_kernel(const float* __restrict__ n,
                 const float* __restrict__ Wsd, const float* __restrict__ bsd,
                 const float* __restrict__ Wpd, const float* __restrict__ bpd,
                 float* __restrict__ sd, float* __restrict__ pd)
{
    int row = blockIdx.x;
    __shared__ float nr[DMdim];
    int tid = threadIdx.x;
    nr[tid] = n[(size_t)row * DMdim + tid];
    __syncthreads();
    int w = tid >> 5, lane = tid & 31;
    const float* Wt = (w < 8) ? (Wsd + (size_t)w * DMdim) : (Wpd + (size_t)(w - 8) * DMdim);
    float acc = 0.f;
    #pragma unroll
    for (int j = lane; j < DMdim; j += 32) acc += nr[j] * Wt[j];
    #pragma unroll
    for (int o = 16; o > 0; o >>= 1) acc += __shfl_xor_sync(0xffffffffu, acc, o);
    if (lane == 0) {
        int h = w & 7;
        float bias = (w < 8) ? bsd[h] : bpd[h];
        float v = 1.f / (1.f + expf(-(acc + bias)));
        if (w < 8) sd[(size_t)row * Hh + h] = v;
        else       pd[(size_t)row * Hh + h] = v;
    }
}

// ---------------- tf32 tensor-core GEMM: cp.async + ldmatrix ----------------
// C[M,N] = A[M,K] @ B[N,K]^T. BM=BN=128, BK=16, 256 threads, 8 warps (4m x 2n).
// Raw fp32 bits fed to tf32 mma (HW truncates). Rows padded to 20 floats (80B)
// => conflict-free ldmatrix and 16B-aligned cp.async rows.
enum { EPI_TANH = 0, EPI_RES = 1, EPI_BIAS_GELU = 2, EPI_BIAS_RES = 3 };

#define ROWF 20        // floats per smem row (16 data + 4 pad)
#define STAGEB (128*ROWF*4)   // bytes per matrix per stage

__device__ __forceinline__ float fast_tanh(float x) {
    float y;
    asm("tanh.approx.f32 %0, %1;" : "=f"(y) : "f"(x));
    return y;
}
__device__ __forceinline__ void ldsm4(unsigned& r0, unsigned& r1,
                                      unsigned& r2, unsigned& r3, unsigned addr) {
    asm volatile("ldmatrix.sync.aligned.m8n8.x4.shared.b16 {%0,%1,%2,%3}, [%4];"
                 : "=r"(r0), "=r"(r1), "=r"(r2), "=r"(r3) : "r"(addr));
}

template<int EPI>
__global__ __launch_bounds__(256)
void mma_gemm_kernel(const float* __restrict__ A, const float* __restrict__ Bw,
                     const float* __restrict__ bias, const float* __restrict__ resid,
                     float* __restrict__ C, int N, int K)
{
    const int BK = 16;
    __shared__ float As[2][128][ROWF];
    __shared__ float Bs[2][128][ROWF];
    int tid  = threadIdx.x;
    int warp = tid >> 5, lane = tid & 31;
    int gq = lane >> 2, tg = lane & 3;
    int wm = warp & 3, wn = warp >> 2;
    int bn0 = blockIdx.x * 128, bm0 = blockIdx.y * 128;

    unsigned asA = (unsigned)__cvta_generic_to_shared(&As[0][0][0]);
    unsigned asB = (unsigned)__cvta_generic_to_shared(&Bs[0][0][0]);

    // ldmatrix per-thread row addresses (bytes), within stage 0:
    // A matrices: mi=lane>>3: row = wm*32 + (mi&1)*8 + (lane&7), koff = (mi>>1)*4 floats
    unsigned aAddr = asA + (unsigned)((wm * 32 + ((lane >> 3) & 1) * 8 + (lane & 7)) * ROWF
                                      + ((lane >> 4) & 1) * 4) * 4u;
    // B matrices: mi=lane>>3: row = wn*64 + (mi>>1)*8 + (lane&7), koff = (mi&1)*4 floats
    unsigned bAddr = asB + (unsigned)((wn * 64 + ((lane >> 4) & 1) * 8 + (lane & 7)) * ROWF
                                      + ((lane >> 3) & 1) * 4) * 4u;

    float acc[2][8][4];
    #pragma unroll
    for (int i = 0; i < 2; i++)
        #pragma unroll
        for (int j = 0; j < 8; j++)
            #pragma unroll
            for (int q = 0; q < 4; q++) acc[i][j][q] = 0.f;

    // cp.async tile load: 512 16B-chunks per matrix; 2 per thread per matrix
    int cm = tid >> 2;             // row (0..63) then +64
    int cc = (tid & 3) * 4;        // float offset within row
    auto CPA = [&](int k0, int bf) {
        #pragma unroll
        for (int c = 0; c < 2; c++) {
            int m = cm + c * 64;
            unsigned da = asA + (unsigned)bf * STAGEB + (unsigned)(m * ROWF + cc) * 4u;
            const float* ga = A + (size_t)(bm0 + m) * K + k0 + cc;
            asm volatile("cp.async.cg.shared.global [%0], [%1], 16;" :: "r"(da), "l"(ga));
            unsigned db = asB + (unsigned)bf * STAGEB + (unsigned)(m * ROWF + cc) * 4u;
            const float* gb = Bw + (size_t)(bn0 + m) * K + k0 + cc;
            asm volatile("cp.async.cg.shared.global [%0], [%1], 16;" :: "r"(db), "l"(gb));
        }
        asm volatile("cp.async.commit_group;");
    };

    CPA(0, 0);
    int NIT = K / BK;
    int buf = 0;
    for (int it = 0; it < NIT; it++) {
        asm volatile("cp.async.wait_group 0;");
        __syncthreads();
        if (it + 1 < NIT) CPA((it + 1) * BK, buf ^ 1);

        unsigned bo = (unsigned)buf * STAGEB;
        #pragma unroll
        for (int s = 0; s < 2; s++) {
            unsigned so = s * 32u;           // +8 floats k offset
            unsigned af[2][4];
            #pragma unroll
            for (int i = 0; i < 2; i++)
                ldsm4(af[i][0], af[i][1], af[i][2], af[i][3],
                      aAddr + bo + so + (unsigned)(i * 16 * ROWF * 4));
            unsigned bfr[8][2];
            #pragma unroll
            for (int j2 = 0; j2 < 4; j2++) {
                unsigned r0, r1, r2, r3;
                ldsm4(r0, r1, r2, r3, bAddr + bo + so + (unsigned)(j2 * 16 * ROWF * 4));
                bfr[j2*2][0] = r0; bfr[j2*2][1] = r1;
                bfr[j2*2+1][0] = r2; bfr[j2*2+1][1] = r3;
            }
            #pragma unroll
            for (int i = 0; i < 2; i++)
                #pragma unroll
                for (int j = 0; j < 8; j++) {
                    asm volatile(
                        "mma.sync.aligned.m16n8k8.row.col.f32.tf32.tf32.f32 "
                        "{%0,%1,%2,%3}, {%4,%5,%6,%7}, {%8,%9}, {%0,%1,%2,%3};"
                        : "+f"(acc[i][j][0]), "+f"(acc[i][j][1]),
                          "+f"(acc[i][j][2]), "+f"(acc[i][j][3])
                        : "r"(af[i][0]), "r"(af[i][1]), "r"(af[i][2]), "r"(af[i][3]),
                          "r"(bfr[j][0]), "r"(bfr[j][1]));
                }
        }
        __syncthreads();
        buf ^= 1;
    }

    #pragma unroll
    for (int i = 0; i < 2; i++) {
        int r0 = bm0 + wm * 32 + i * 16 + gq;
        #pragma unroll
        for (int j = 0; j < 8; j++) {
            int col = bn0 + wn * 64 + j * 8 + tg * 2;
            #pragma unroll
            for (int half = 0; half < 2; half++) {
                int row = r0 + half * 8;
                float v0 = acc[i][j][half * 2 + 0];
                float v1 = acc[i][j][half * 2 + 1];
                if (EPI == EPI_BIAS_GELU || EPI == EPI_BIAS_RES) {
                    v0 += bias[col]; v1 += bias[col + 1];
                }
                if (EPI == EPI_TANH) { v0 = fast_tanh(v0); v1 = fast_tanh(v1); }
                if (EPI == EPI_BIAS_GELU) {
                    v0 = 0.5f * v0 * (1.f + erff(v0 * 0.70710678118654752f));
                    v1 = 0.5f * v1 * (1.f + erff(v1 * 0.70710678118654752f));
                }
                if (EPI == EPI_RES || EPI == EPI_BIAS_RES) {
                    float2 rv = *(const float2*)(resid + (size_t)row * N + col);
                    v0 += rv.x; v1 += rv.y;
                }
                float2 o = {v0, v1};
                *(float2*)(C + (size_t)row * N + col) = o;
            }
        }
    }
}

// ---------------- pair-state scan: chunked smem pipeline ----------------
#define SCHUNK 16
__global__ __launch_bounds__(256)
void pair_scan_kernel(const float* __restrict__ a,  const float* __restrict__ bm,
                      const float* __restrict__ ql, const float* __restrict__ qr,
                      const float* __restrict__ sd, const float* __restrict__ pd,
                      float* __restrict__ g)
{
    int blk = blockIdx.x;
    int eh  = blk & 1;
    int bh  = blk >> 1;
    int tid = threadIdx.x;
    int el  = tid >> 3;
    int dq  = tid & 7;

    __shared__ float sa [2][SCHUNK][64];
    __shared__ float sq [2][SCHUNK][64];
    __shared__ float sbh[2][SCHUNK][32];
    __shared__ float srh[2][SCHUNK][32];
    __shared__ float ssd[2][SCHUNK];
    __shared__ float spd[2][SCHUNK];

    size_t base0  = (size_t)(bh >> 3) * Ssz * INNER + (size_t)(bh & 7) * SDdim;
    size_t base80 = (size_t)(bh >> 3) * Ssz * Hh + (bh & 7);

    int tA = tid >> 4, fA = tid & 15;
    int tB = (tid & 127) >> 3, fB = tid & 7;
    bool loB = tid < 128;
    bool loSd = tid < SCHUNK;
    bool loPd = tid >= 32 && tid < 32 + SCHUNK;

    float4 rA, rQ, rH;
    float  rS = 0.f;

    auto LOADC = [&](int c) {
        size_t bs = base0 + (size_t)c * SCHUNK * INNER;
        size_t b8 = base80 + (size_t)c * SCHUNK * Hh;
        rA = *(const float4*)(a  + bs + (size_t)tA * INNER + fA * 4);
        rQ = *(const float4*)(ql + bs + (size_t)tA * INNER + fA * 4);
        const float* hsrc = loB ? bm : qr;
        rH = *(const float4*)(hsrc + bs + (size_t)tB * INNER + eh * 32 + fB * 4);
        if (loSd)      rS = sd[b8 + (size_t)tid * Hh];
        else if (loPd) rS = pd[b8 + (size_t)(tid - 32) * Hh];
    };
    auto STOREC = [&](int bf) {
        *(float4*)&sa[bf][tA][fA * 4] = rA;
        *(float4*)&sq[bf][tA][fA * 4] = rQ;
        if (loB) *(float4*)&sbh[bf][tB][fB * 4] = rH;
        else     *(float4*)&srh[bf][tB][fB * 4] = rH;
        if (loSd)      ssd[bf][tid]      = rS;
        else if (loPd) spd[bf][tid - 32] = rS;
    };

    float p[8], st[8];
    #pragma unroll
    for (int i = 0; i < 8; i++) { p[i] = 0.f; st[i] = 0.f; }

    LOADC(0);
    STOREC(0);
    __syncthreads();

    const int NC = Ssz / SCHUNK;
    int buf = 0;
    size_t gbase = base0 + eh * 32 + el;

    for (int c = 0; c < NC; c++) {
        bool more = (c + 1) < NC;
        if (more) LOADC(c + 1);

        #pragma unroll 4
        for (int t = 0; t < SCHUNK; t++) {
            float sdv = ssd[buf][t];
            float pdv = spd[buf][t];
            float cc  = (1.f - pdv) * sbh[buf][t][el];
            float4 q0 = *(const float4*)&sq[buf][t][dq * 8];
            float4 q1 = *(const float4*)&sq[buf][t][dq * 8 + 4];
            float4 a0 = *(const float4*)&sa[buf][t][dq * 8];
            float4 a1 = *(const float4*)&sa[buf][t][dq * 8 + 4];
            float qv[8] = {q0.x,q0.y,q0.z,q0.w,q1.x,q1.y,q1.z,q1.w};
            float av[8] = {a0.x,a0.y,a0.z,a0.w,a1.x,a1.y,a1.z,a1.w};

            float lacc = 0.f;
            #pragma unroll
            for (int i = 0; i < 8; i++) {
                p[i] = pdv * p[i] + cc * st[i];
                lacc += p[i] * qv[i];
            }
            float om = 1.f - sdv;
            #pragma unroll
            for (int i = 0; i < 8; i++)
                st[i] = sdv * st[i] + om * av[i];

            lacc += __shfl_xor_sync(0xffffffffu, lacc, 1);
            lacc += __shfl_xor_sync(0xffffffffu, lacc, 2);
            lacc += __shfl_xor_sync(0xffffffffu, lacc, 4);
            if (dq == 0) g[gbase + (size_t)t * INNER] = lacc * srh[buf][t][el];
        }

        if (more) STOREC(buf ^ 1);
        __syncthreads();
        buf ^= 1;
        gbase += (size_t)SCHUNK * INNER;
    }
}

// ---------------- launch ----------------
extern "C" void kernel_launch(void* const* d_in, const int* in_sizes, int n_in,
                              void* d_out, int out_size)
{
    const float* x    = (const float*)d_in[0];
    const float* ng   = (const float*)d_in[1];
    const float* nb   = (const float*)d_in[2];
    const float* fng  = (const float*)d_in[3];
    const float* fnb  = (const float*)d_in[4];
    const float* Wa   = (const float*)d_in[5];
    const float* Wb   = (const float*)d_in[6];
    const float* Wql  = (const float*)d_in[7];
    const float* Wqr  = (const float*)d_in[8];
    const float* Wsd  = (const float*)d_in[9];
    const float* bsd  = (const float*)d_in[10];
    const float* Wpd  = (const float*)d_in[11];
    const float* bpd  = (const float*)d_in[12];
    const float* Wout = (const float*)d_in[13];
    const float* W1   = (const float*)d_in[14];
    const float* b1   = (const float*)d_in[15];
    const float* W2   = (const float*)d_in[16];
    const float* b2   = (const float*)d_in[17];
    float* out = (float*)d_out;

    float *pn, *pa, *pb, *pql, *pqr, *psd, *ppd, *pg, *pr, *pl2, *ph;
    cudaGetSymbolAddress((void**)&pn,  g_n);
    cudaGetSymbolAddress((void**)&pa,  g_a);
    cudaGetSymbolAddress((void**)&pb,  g_b);
    cudaGetSymbolAddress((void**)&pql, g_ql);
    cudaGetSymbolAddress((void**)&pqr, g_qr);
    cudaGetSymbolAddress((void**)&psd, g_sd);
    cudaGetSymbolAddress((void**)&ppd, g_pd);
    cudaGetSymbolAddress((void**)&pg,  g_g);
    cudaGetSymbolAddress((void**)&pr,  g_r);
    cudaGetSymbolAddress((void**)&pl2, g_l2);
    cudaGetSymbolAddress((void**)&ph,  g_h);

    // 1) n = LN(x)
    ln_kernel<<<MROWS, 128>>>(x, ng, nb, pn);

    // 2) tanh projections (M=16384, N=512, K=512) on tensor cores
    dim3 gp(INNER / 128, MROWS / 128);
    mma_gemm_kernel<EPI_TANH><<<gp, 256>>>(pn, Wa,  nullptr, nullptr, pa,  INNER, DMdim);
    mma_gemm_kernel<EPI_TANH><<<gp, 256>>>(pn, Wb,  nullptr, nullptr, pb,  INNER, DMdim);
    mma_gemm_kernel<EPI_TANH><<<gp, 256>>>(pn, Wql, nullptr, nullptr, pql, INNER, DMdim);
    mma_gemm_kernel<EPI_TANH><<<gp, 256>>>(pn, Wqr, nullptr, nullptr, pqr, INNER, DMdim);

    // 3) sigmoid gates
    sdpd_kernel<<<MROWS, 512>>>(pn, Wsd, bsd, Wpd, bpd, psd, ppd);

    // 4) pair-state scan -> g = lc * qr
    pair_scan_kernel<<<128, 256>>>(pa, pb, pql, pqr, psd, ppd, pg);

    // 5) r = x + g @ Wout^T
    mma_gemm_kernel<EPI_RES><<<dim3(DMdim / 128, MROWS / 128), 256>>>(
        pg, Wout, nullptr, x, pr, DMdim, INNER);

    // 6) ln2 = LN(r)
    ln_kernel<<<MROWS, 128>>>(pr, fng, fnb, pl2);

    // 7) h = gelu(ln2 @ W1^T + b1)
    mma_gemm_kernel<EPI_BIAS_GELU><<<dim3(HID / 128, MROWS / 128), 256>>>(
        pl2, W1, b1, nullptr, ph, HID, DMdim);

    // 8) out = r + h @ W2^T + b2
    mma_gemm_kernel<EPI_BIAS_RES><<<dim3(DMdim / 128, MROWS / 128), 256>>>(
        ph, W2, b2, pr, out, DMdim, HID);
}

// round 6
// speedup vs baseline: 3.8235x; 1.0232x over previous
#include <cuda_runtime.h>
#include <math.h>

// Problem dims
#define Bsz   8
#define Ssz   2048
#define DMdim 512
#define Hh    8
#define SDdim 64
#define INNER 512
#define HID   2048
#define MROWS (Bsz*Ssz)   // 16384

// ---------------- scratch (device globals: allocation-free) ----------------
__device__ float g_n [MROWS*DMdim];
__device__ float g_a [MROWS*INNER];
__device__ float g_b [MROWS*INNER];
__device__ float g_ql[MROWS*INNER];
__device__ float g_qr[MROWS*INNER];
__device__ float g_sd[MROWS*Hh];
__device__ float g_pd[MROWS*Hh];
__device__ float g_g [MROWS*INNER];
__device__ float g_r [MROWS*DMdim];
__device__ float g_l2[MROWS*DMdim];
__device__ float g_h [MROWS*HID];

// ---------------- LayerNorm ----------------
__global__ __launch_bounds__(128)
void ln_kernel(const float* __restrict__ x, const float* __restrict__ gm,
               const float* __restrict__ bt, float* __restrict__ out)
{
    int row = blockIdx.x;
    int tid = threadIdx.x;
    const float4* xr = (const float4*)(x + (size_t)row * DMdim);
    float4 v = xr[tid];
    float s  = v.x + v.y + v.z + v.w;
    float s2 = v.x*v.x + v.y*v.y + v.z*v.z + v.w*v.w;
    #pragma unroll
    for (int o = 16; o > 0; o >>= 1) {
        s  += __shfl_xor_sync(0xffffffffu, s,  o);
        s2 += __shfl_xor_sync(0xffffffffu, s2, o);
    }
    __shared__ float ss[4], ss2[4];
    int wid = tid >> 5, lane = tid & 31;
    if (lane == 0) { ss[wid] = s; ss2[wid] = s2; }
    __syncthreads();
    s  = ss[0] + ss[1] + ss[2] + ss[3];
    s2 = ss2[0] + ss2[1] + ss2[2] + ss2[3];
    float m   = s * (1.0f / DMdim);
    float var = s2 * (1.0f / DMdim) - m * m;
    float inv = rsqrtf(var + 1e-5f);
    float4 gv = ((const float4*)gm)[tid];
    float4 bv = ((const float4*)bt)[tid];
    float4 o;
    o.x = (v.x - m) * inv * gv.x + bv.x;
    o.y = (v.y - m) * inv * gv.y + bv.y;
    o.z = (v.z - m) * inv * gv.z + bv.z;
    o.w = (v.w - m) * inv * gv.w + bv.w;
    ((float4*)(out + (size_t)row * DMdim))[tid] = o;
}

// ---------------- sd/pd gates ----------------
__global__ __launch_bounds__(512)
void sdpd_kernel(const float* __restrict__ n,
                 const float* __restrict__ Wsd, const float* __restrict__ bsd,
                 const float* __restrict__ Wpd, const float* __restrict__ bpd,
                 float* __restrict__ sd, float* __restrict__ pd)
{
    int row = blockIdx.x;
    __shared__ float nr[DMdim];
    int tid = threadIdx.x;
    nr[tid] = n[(size_t)row * DMdim + tid];
    __syncthreads();
    int w = tid >> 5, lane = tid & 31;
    const float* Wt = (w < 8) ? (Wsd + (size_t)w * DMdim) : (Wpd + (size_t)(w - 8) * DMdim);
    float acc = 0.f;
    #pragma unroll
    for (int j = lane; j < DMdim; j += 32) acc += nr[j] * Wt[j];
    #pragma unroll
    for (int o = 16; o > 0; o >>= 1) acc += __shfl_xor_sync(0xffffffffu, acc, o);
    if (lane == 0) {
        int h = w & 7;
        float bias = (w < 8) ? bsd[h] : bpd[h];
        float v = 1.f / (1.f + expf(-(acc + bias)));
        if (w < 8) sd[(size_t)row * Hh + h] = v;
        else       pd[(size_t)row * Hh + h] = v;
    }
}

// ---------------- tf32 tensor-core GEMM: 4-stage cp.async + ldmatrix ----------
// C[M,N] = A[M,K] @ B[N,K]^T. BM=BN=128, BK=16, 256 threads, 8 warps (4m x 2n).
// gridDim.z selects one of up to 4 (weight, output) pairs (fused projections).
enum { EPI_TANH = 0, EPI_RES = 1, EPI_BIAS_GELU = 2, EPI_BIAS_RES = 3 };

#define ROWF   20                    // floats per smem row (16 data + 4 pad)
#define STAGEB (128*ROWF*4)          // bytes per matrix per stage = 10240
#define STAGES 4
#define GEMM_SMEM (STAGES*2*STAGEB)  // 81920 bytes

__device__ __forceinline__ float fast_tanh(float x) {
    float y;
    asm("tanh.approx.f32 %0, %1;" : "=f"(y) : "f"(x));
    return y;
}
__device__ __forceinline__ void ldsm4(unsigned& r0, unsigned& r1,
                                      unsigned& r2, unsigned& r3, unsigned addr) {
    asm volatile("ldmatrix.sync.aligned.m8n8.x4.shared.b16 {%0,%1,%2,%3}, [%4];"
                 : "=r"(r0), "=r"(r1), "=r"(r2), "=r"(r3) : "r"(addr));
}

template<int EPI>
__global__ __launch_bounds__(256)
void mma_gemm_kernel(const float* __restrict__ A,
                     const float* __restrict__ w0, const float* __restrict__ w1,
                     const float* __restrict__ w2, const float* __restrict__ w3,
                     const float* __restrict__ bias, const float* __restrict__ resid,
                     float* c0, float* c1, float* c2, float* c3,
                     int N, int K)
{
    const int BK = 16;
    extern __shared__ __align__(16) float smem[];
    int z = blockIdx.z;
    const float* Bw = (z == 0) ? w0 : (z == 1) ? w1 : (z == 2) ? w2 : w3;
    float*       C  = (z == 0) ? c0 : (z == 1) ? c1 : (z == 2) ? c2 : c3;

    int tid  = threadIdx.x;
    int warp = tid >> 5, lane = tid & 31;
    int gq = lane >> 2, tg = lane & 3;
    int wm = warp & 3, wn = warp >> 2;
    int bn0 = blockIdx.x * 128, bm0 = blockIdx.y * 128;

    unsigned asA = (unsigned)__cvta_generic_to_shared(smem);
    unsigned asB = asA + STAGES * STAGEB;

    unsigned aAddr = asA + (unsigned)((wm * 32 + ((lane >> 3) & 1) * 8 + (lane & 7)) * ROWF
                                      + ((lane >> 4) & 1) * 4) * 4u;
    unsigned bAddr = asB + (unsigned)((wn * 64 + ((lane >> 4) & 1) * 8 + (lane & 7)) * ROWF
                                      + ((lane >> 3) & 1) * 4) * 4u;

    float acc[2][8][4];
    #pragma unroll
    for (int i = 0; i < 2; i++)
        #pragma unroll
        for (int j = 0; j < 8; j++)
            #pragma unroll
            for (int q = 0; q < 4; q++) acc[i][j][q] = 0.f;

    int cm = tid >> 2;
    int cc = (tid & 3) * 4;
    auto CPA = [&](int k0, int bf) {
        #pragma unroll
        for (int c = 0; c < 2; c++) {
            int m = cm + c * 64;
            unsigned da = asA + (unsigned)bf * STAGEB + (unsigned)(m * ROWF + cc) * 4u;
            const float* ga = A + (size_t)(bm0 + m) * K + k0 + cc;
            asm volatile("cp.async.cg.shared.global [%0], [%1], 16;" :: "r"(da), "l"(ga));
            unsigned db = asB + (unsigned)bf * STAGEB + (unsigned)(m * ROWF + cc) * 4u;
            const float* gb = Bw + (size_t)(bn0 + m) * K + k0 + cc;
            asm volatile("cp.async.cg.shared.global [%0], [%1], 16;" :: "r"(db), "l"(gb));
        }
        asm volatile("cp.async.commit_group;");
    };

    int NIT = K / BK;
    #pragma unroll
    for (int s = 0; s < STAGES - 1; s++) CPA(s * BK, s);

    int buf = 0;
    for (int it = 0; it < NIT; it++) {
        asm volatile("cp.async.wait_group %0;" :: "n"(STAGES - 2));
        __syncthreads();
        int nk = it + STAGES - 1;
        if (nk < NIT) CPA(nk * BK, nk & (STAGES - 1));

        unsigned bo = (unsigned)buf * STAGEB;
        #pragma unroll
        for (int s = 0; s < 2; s++) {
            unsigned so = s * 32u;
            unsigned af[2][4];
            #pragma unroll
            for (int i = 0; i < 2; i++)
                ldsm4(af[i][0], af[i][1], af[i][2], af[i][3],
                      aAddr + bo + so + (unsigned)(i * 16 * ROWF * 4));
            unsigned bfr[8][2];
            #pragma unroll
            for (int j2 = 0; j2 < 4; j2++) {
                unsigned r0, r1, r2, r3;
                ldsm4(r0, r1, r2, r3, bAddr + bo + so + (unsigned)(j2 * 16 * ROWF * 4));
                bfr[j2*2][0] = r0; bfr[j2*2][1] = r1;
                bfr[j2*2+1][0] = r2; bfr[j2*2+1][1] = r3;
            }
            #pragma unroll
            for (int i = 0; i < 2; i++)
                #pragma unroll
                for (int j = 0; j < 8; j++) {
                    asm volatile(
                        "mma.sync.aligned.m16n8k8.row.col.f32.tf32.tf32.f32 "
                        "{%0,%1,%2,%3}, {%4,%5,%6,%7}, {%8,%9}, {%0,%1,%2,%3};"
                        : "+f"(acc[i][j][0]), "+f"(acc[i][j][1]),
                          "+f"(acc[i][j][2]), "+f"(acc[i][j][3])
                        : "r"(af[i][0]), "r"(af[i][1]), "r"(af[i][2]), "r"(af[i][3]),
                          "r"(bfr[j][0]), "r"(bfr[j][1]));
                }
        }
        buf = (buf + 1) & (STAGES - 1);
    }

    #pragma unroll
    for (int i = 0; i < 2; i++) {
        int r0 = bm0 + wm * 32 + i * 16 + gq;
        #pragma unroll
        for (int j = 0; j < 8; j++) {
            int col = bn0 + wn * 64 + j * 8 + tg * 2;
            #pragma unroll
            for (int half = 0; half < 2; half++) {
                int row = r0 + half * 8;
                float v0 = acc[i][j][half * 2 + 0];
                float v1 = acc[i][j][half * 2 + 1];
                if (EPI == EPI_BIAS_GELU || EPI == EPI_BIAS_RES) {
                    v0 += bias[col]; v1 += bias[col + 1];
                }
                if (EPI == EPI_TANH) { v0 = fast_tanh(v0); v1 = fast_tanh(v1); }
                if (EPI == EPI_BIAS_GELU) {
                    v0 = 0.5f * v0 * (1.f + erff(v0 * 0.70710678118654752f));
                    v1 = 0.5f * v1 * (1.f + erff(v1 * 0.70710678118654752f));
                }
                if (EPI == EPI_RES || EPI == EPI_BIAS_RES) {
                    float2 rv = *(const float2*)(resid + (size_t)row * N + col);
                    v0 += rv.x; v1 += rv.y;
                }
                float2 o = {v0, v1};
                *(float2*)(C + (size_t)row * N + col) = o;
            }
        }
    }
}

// ---------------- pair-state scan: chunked smem pipeline ----------------
#define SCHUNK 16
__global__ __launch_bounds__(256)
void pair_scan_kernel(const float* __restrict__ a,  const float* __restrict__ bm,
                      const float* __restrict__ ql, const float* __restrict__ qr,
                      const float* __restrict__ sd, const float* __restrict__ pd,
                      float* __restrict__ g)
{
    int blk = blockIdx.x;
    int eh  = blk & 1;
    int bh  = blk >> 1;
    int tid = threadIdx.x;
    int el  = tid >> 3;
    int dq  = tid & 7;

    __shared__ float sa [2][SCHUNK][64];
    __shared__ float sq [2][SCHUNK][64];
    __shared__ float sbh[2][SCHUNK][32];
    __shared__ float srh[2][SCHUNK][32];
    __shared__ float ssd[2][SCHUNK];
    __shared__ float spd[2][SCHUNK];

    size_t base0  = (size_t)(bh >> 3) * Ssz * INNER + (size_t)(bh & 7) * SDdim;
    size_t base80 = (size_t)(bh >> 3) * Ssz * Hh + (bh & 7);

    int tA = tid >> 4, fA = tid & 15;
    int tB = (tid & 127) >> 3, fB = tid & 7;
    bool loB = tid < 128;
    bool loSd = tid < SCHUNK;
    bool loPd = tid >= 32 && tid < 32 + SCHUNK;

    float4 rA, rQ, rH;
    float  rS = 0.f;

    auto LOADC = [&](int c) {
        size_t bs = base0 + (size_t)c * SCHUNK * INNER;
        size_t b8 = base80 + (size_t)c * SCHUNK * Hh;
        rA = *(const float4*)(a  + bs + (size_t)tA * INNER + fA * 4);
        rQ = *(const float4*)(ql + bs + (size_t)tA * INNER + fA * 4);
        const float* hsrc = loB ? bm : qr;
        rH = *(const float4*)(hsrc + bs + (size_t)tB * INNER + eh * 32 + fB * 4);
        if (loSd)      rS = sd[b8 + (size_t)tid * Hh];
        else if (loPd) rS = pd[b8 + (size_t)(tid - 32) * Hh];
    };
    auto STOREC = [&](int bf) {
        *(float4*)&sa[bf][tA][fA * 4] = rA;
        *(float4*)&sq[bf][tA][fA * 4] = rQ;
        if (loB) *(float4*)&sbh[bf][tB][fB * 4] = rH;
        else     *(float4*)&srh[bf][tB][fB * 4] = rH;
        if (loSd)      ssd[bf][tid]      = rS;
        else if (loPd) spd[bf][tid - 32] = rS;
    };

    float p[8], st[8];
    #pragma unroll
    for (int i = 0; i < 8; i++) { p[i] = 0.f; st[i] = 0.f; }

    LOADC(0);
    STOREC(0);
    __syncthreads();

    const int NC = Ssz / SCHUNK;
    int buf = 0;
    size_t gbase = base0 + eh * 32 + el;

    for (int c = 0; c < NC; c++) {
        bool more = (c + 1) < NC;
        if (more) LOADC(c + 1);

        #pragma unroll 4
        for (int t = 0; t < SCHUNK; t++) {
            float sdv = ssd[buf][t];
            float pdv = spd[buf][t];
            float cc  = (1.f - pdv) * sbh[buf][t][el];
            float4 q0 = *(const float4*)&sq[buf][t][dq * 8];
            float4 q1 = *(const float4*)&sq[buf][t][dq * 8 + 4];
            float4 a0 = *(const float4*)&sa[buf][t][dq * 8];
            float4 a1 = *(const float4*)&sa[buf][t][dq * 8 + 4];
            float qv[8] = {q0.x,q0.y,q0.z,q0.w,q1.x,q1.y,q1.z,q1.w};
            float av[8] = {a0.x,a0.y,a0.z,a0.w,a1.x,a1.y,a1.z,a1.w};

            float lacc = 0.f;
            #pragma unroll
            for (int i = 0; i < 8; i++) {
                p[i] = pdv * p[i] + cc * st[i];
                lacc += p[i] * qv[i];
            }
            float om = 1.f - sdv;
            #pragma unroll
            for (int i = 0; i < 8; i++)
                st[i] = sdv * st[i] + om * av[i];

            lacc += __shfl_xor_sync(0xffffffffu, lacc, 1);
            lacc += __shfl_xor_sync(0xffffffffu, lacc, 2);
            lacc += __shfl_xor_sync(0xffffffffu, lacc, 4);
            if (dq == 0) g[gbase + (size_t)t * INNER] = lacc * srh[buf][t][el];
        }

        if (more) STOREC(buf ^ 1);
        __syncthreads();
        buf ^= 1;
        gbase += (size_t)SCHUNK * INNER;
    }
}

// ---------------- launch ----------------
extern "C" void kernel_launch(void* const* d_in, const int* in_sizes, int n_in,
                              void* d_out, int out_size)
{
    const float* x    = (const float*)d_in[0];
    const float* ng   = (const float*)d_in[1];
    const float* nb   = (const float*)d_in[2];
    const float* fng  = (const float*)d_in[3];
    const float* fnb  = (const float*)d_in[4];
    const float* Wa   = (const float*)d_in[5];
    const float* Wb   = (const float*)d_in[6];
    const float* Wql  = (const float*)d_in[7];
    const float* Wqr  = (const float*)d_in[8];
    const float* Wsd  = (const float*)d_in[9];
    const float* bsd  = (const float*)d_in[10];
    const float* Wpd  = (const float*)d_in[11];
    const float* bpd  = (const float*)d_in[12];
    const float* Wout = (const float*)d_in[13];
    const float* W1   = (const float*)d_in[14];
    const float* b1   = (const float*)d_in[15];
    const float* W2   = (const float*)d_in[16];
    const float* b2   = (const float*)d_in[17];
    float* out = (float*)d_out;

    float *pn, *pa, *pb, *pql, *pqr, *psd, *ppd, *pg, *pr, *pl2, *ph;
    cudaGetSymbolAddress((void**)&pn,  g_n);
    cudaGetSymbolAddress((void**)&pa,  g_a);
    cudaGetSymbolAddress((void**)&pb,  g_b);
    cudaGetSymbolAddress((void**)&pql, g_ql);
    cudaGetSymbolAddress((void**)&pqr, g_qr);
    cudaGetSymbolAddress((void**)&psd, g_sd);
    cudaGetSymbolAddress((void**)&ppd, g_pd);
    cudaGetSymbolAddress((void**)&pg,  g_g);
    cudaGetSymbolAddress((void**)&pr,  g_r);
    cudaGetSymbolAddress((void**)&pl2, g_l2);
    cudaGetSymbolAddress((void**)&ph,  g_h);

    cudaFuncSetAttribute(mma_gemm_kernel<EPI_TANH>,
                         cudaFuncAttributeMaxDynamicSharedMemorySize, GEMM_SMEM);
    cudaFuncSetAttribute(mma_gemm_kernel<EPI_RES>,
                         cudaFuncAttributeMaxDynamicSharedMemorySize, GEMM_SMEM);
    cudaFuncSetAttribute(mma_gemm_kernel<EPI_BIAS_GELU>,
                         cudaFuncAttributeMaxDynamicSharedMemorySize, GEMM_SMEM);
    cudaFuncSetAttribute(mma_gemm_kernel<EPI_BIAS_RES>,
                         cudaFuncAttributeMaxDynamicSharedMemorySize, GEMM_SMEM);

    // 1) n = LN(x)
    ln_kernel<<<MROWS, 128>>>(x, ng, nb, pn);

    // 2) fused tanh projections: one launch, z selects (W, out)
    dim3 gp(INNER / 128, MROWS / 128, 4);
    mma_gemm_kernel<EPI_TANH><<<gp, 256, GEMM_SMEM>>>(
        pn, Wa, Wb, Wql, Wqr, nullptr, nullptr, pa, pb, pql, pqr, INNER, DMdim);

    // 3) sigmoid gates
    sdpd_kernel<<<MROWS, 512>>>(pn, Wsd, bsd, Wpd, bpd, psd, ppd);

    // 4) pair-state scan -> g = lc * qr
    pair_scan_kernel<<<128, 256>>>(pa, pb, pql, pqr, psd, ppd, pg);

    // 5) r = x + g @ Wout^T
    mma_gemm_kernel<EPI_RES><<<dim3(DMdim / 128, MROWS / 128, 1), 256, GEMM_SMEM>>>(
        pg, Wout, Wout, Wout, Wout, nullptr, x, pr, pr, pr, pr, DMdim, INNER);

    // 6) ln2 = LN(r)
    ln_kernel<<<MROWS, 128>>>(pr, fng, fnb, pl2);

    // 7) h = gelu(ln2 @ W1^T + b1)
    mma_gemm_kernel<EPI_BIAS_GELU><<<dim3(HID / 128, MROWS / 128, 1), 256, GEMM_SMEM>>>(
        pl2, W1, W1, W1, W1, b1, nullptr, ph, ph, ph, ph, HID, DMdim);

    // 8) out = r + h @ W2^T + b2
    mma_gemm_kernel<EPI_BIAS_RES><<<dim3(DMdim / 128, MROWS / 128, 1), 256, GEMM_SMEM>>>(
        ph, W2, W2, W2, W2, b2, pr, out, out, out, out, DMdim, HID);
}